// round 12
// baseline (speedup 1.0000x reference)
#include <cuda_runtime.h>
#include <cuda_bf16.h>

// ChamferDist via x-binned pruned NN search.
// d^2 = |q|^2 + (|s|^2 - 2 q.s); refs stored pre-transformed & duplicated for
// packed f32x2 FMA. Bins are fixed-width in x over [-4.5,4.5] (tails clamped);
// a block of x-contiguous queries expands outward from its home bin and stops
// a direction when the x-gap to the bin edge exceeds the block's current max
// NN radius. Min over a set is order-invariant -> exact result.
// Final reduction is done by the last cd_main block (deterministic fixed-order
// sum; no float atomics) to avoid a tail grid-1 launch.

#define NB 8
#define NP 4096
#define BINS 128
#define XLO (-4.5f)
#define XW (9.0f / BINS)
#define INVW ((float)BINS / 9.0f)

#define TB 256              // bucket threads
#define TM 128              // main threads
#define TILE_P (TM * 2)     // 256 queries per block
#define PT (NP / TILE_P)    // 16 tiles per (dir,batch)
#define NBLK (2 * NB * PT)  // 256 main blocks
#define STAGE 512           // staged refs per chunk

#define F_INF __int_as_float(0x7F800000)

// Scratch (allocations forbidden).
__device__ float4 g_qry[2 * NB * NP];             // (x,y,z,|n|^2), bucketed
__device__ float4 g_refA[2 * NB * NP];            // (-2x,-2x,-2y,-2y)
__device__ float4 g_refB[2 * NB * NP];            // (-2z,-2z,|s|^2,|s|^2)
__device__ int    g_boff[2 * NB * (BINS + 1)];    // bin start offsets
__device__ float  g_part[NBLK];                   // per-block sqrt-sums
__device__ int    g_ctr;                          // done-block counter

// ---- packed f32x2 helpers ----
__device__ __forceinline__ unsigned long long pack2(float lo, float hi) {
    unsigned long long r;
    asm("mov.b64 %0, {%1, %2};" : "=l"(r) : "f"(lo), "f"(hi));
    return r;
}
__device__ __forceinline__ unsigned long long fma2(unsigned long long a,
                                                   unsigned long long b,
                                                   unsigned long long c) {
    unsigned long long d;
    asm("fma.rn.f32x2 %0, %1, %2, %3;" : "=l"(d) : "l"(a), "l"(b), "l"(c));
    return d;
}
__device__ __forceinline__ void unpack2(unsigned long long v, float& lo, float& hi) {
    asm("mov.b64 {%0, %1}, %2;" : "=f"(lo), "=f"(hi) : "l"(v));
}

__device__ __forceinline__ int bin_of(float x) {
    int b = (int)floorf((x - XLO) * INVW);
    return min(BINS - 1, max(0, b));
}

// One block per (array,batch). arr 0 = tar, arr 1 = src.
__global__ __launch_bounds__(TB) void cd_bucket(const float* __restrict__ tar,
                                                const float* __restrict__ src) {
    __shared__ int scount[BINS];
    __shared__ int soff[BINS + 1];

    int arr = blockIdx.x >> 3, batch = blockIdx.x & 7;
    if (blockIdx.x == 0 && threadIdx.x == 0) g_ctr = 0;  // reset for this graph replay
    const float* in = (arr == 0 ? tar : src) + (size_t)batch * NP * 3;
    int tid = threadIdx.x, lane = tid & 31;

    for (int b = tid; b < BINS; b += TB) scount[b] = 0;
    __syncthreads();

    // pass 1: counts (warp-aggregated atomics)
    for (int i = tid; i < NP; i += TB) {
        int bin = bin_of(in[3 * i]);
        unsigned peers = __match_any_sync(0xffffffffu, bin);
        int leader = __ffs(peers) - 1;
        if (lane == leader) atomicAdd(&scount[bin], __popc(peers));
    }
    __syncthreads();

    if (tid == 0) {
        int acc = 0;
        for (int b = 0; b < BINS; ++b) { soff[b] = acc; acc += scount[b]; }
        soff[BINS] = acc;
    }
    __syncthreads();

    int obase = (arr * NB + batch) * (BINS + 1);
    for (int b = tid; b <= BINS; b += TB) g_boff[obase + b] = soff[b];
    for (int b = tid; b < BINS; b += TB) scount[b] = soff[b];  // running offsets
    __syncthreads();

    // pass 2: scatter (order within bin irrelevant: min/mean are invariant)
    int pbase = (arr * NB + batch) * NP;
    for (int i = tid; i < NP; i += TB) {
        float x = in[3 * i], y = in[3 * i + 1], z = in[3 * i + 2];
        int bin = bin_of(x);
        unsigned peers = __match_any_sync(0xffffffffu, bin);
        int leader = __ffs(peers) - 1;
        int rank = __popc(peers & ((1u << lane) - 1u));
        int base;
        if (lane == leader) base = atomicAdd(&scount[bin], __popc(peers));
        base = __shfl_sync(0xffffffffu, base, leader);
        int slot = pbase + base + rank;
        float n2 = fmaf(x, x, fmaf(y, y, z * z));
        g_qry[slot]  = make_float4(x, y, z, n2);
        g_refA[slot] = make_float4(-2.0f * x, -2.0f * x, -2.0f * y, -2.0f * y);
        g_refB[slot] = make_float4(-2.0f * z, -2.0f * z, n2, n2);
    }
}

// dir 0: queries = tar (arr0), refs = src (arr1) -> complete
// dir 1: queries = src (arr1), refs = tar (arr0) -> accuracy
__global__ __launch_bounds__(TM) void cd_main(float* __restrict__ out) {
    __shared__ float4 stA[STAGE];
    __shared__ float4 stB[STAGE];
    __shared__ int   soff[BINS + 1];
    __shared__ float sred[4];
    __shared__ float sqlo[4], sqhi[4];
    __shared__ int   s_last;

    int bid   = blockIdx.x;
    int tile  = bid % PT;
    int batch = (bid / PT) % NB;
    int dir   = bid / (PT * NB);
    int qarr  = dir;
    int rarr  = 1 - dir;

    int tid = threadIdx.x, lane = tid & 31, wid = tid >> 5;

    int obase = (rarr * NB + batch) * (BINS + 1);
    for (int b = tid; b <= BINS; b += TM) soff[b] = g_boff[obase + b];

    // Load 2 adjacent (x-coherent) queries per thread.
    const float4* qb = g_qry + (qarr * NB + batch) * NP + tile * TILE_P;
    float4 a0 = qb[2 * tid], a1 = qb[2 * tid + 1];
    unsigned long long qx2 = pack2(a0.x, a1.x);
    unsigned long long qy2 = pack2(a0.y, a1.y);
    unsigned long long qz2 = pack2(a0.z, a1.z);
    float qn0 = a0.w, qn1 = a1.w;
    float m0 = F_INF, m1 = F_INF;

    // Block x-range
    float xl = fminf(a0.x, a1.x), xh = fmaxf(a0.x, a1.x);
#pragma unroll
    for (int o = 16; o; o >>= 1) {
        xl = fminf(xl, __shfl_xor_sync(0xffffffffu, xl, o));
        xh = fmaxf(xh, __shfl_xor_sync(0xffffffffu, xh, o));
    }
    if (lane == 0) { sqlo[wid] = xl; sqhi[wid] = xh; }
    __syncthreads();
    float qlo = fminf(fminf(sqlo[0], sqlo[1]), fminf(sqlo[2], sqlo[3]));
    float qhi = fmaxf(fmaxf(sqhi[0], sqhi[1]), fmaxf(sqhi[2], sqhi[3]));

    const float4* refA = g_refA + (rarr * NB + batch) * NP;
    const float4* refB = g_refB + (rarr * NB + batch) * NP;

    // process one bin (block-uniform call)
#define PROCESS_BIN(b)                                                        \
    do {                                                                      \
        int _j0 = soff[(b)], _j1 = soff[(b) + 1];                             \
        for (int _c = _j0; _c < _j1; _c += STAGE) {                           \
            int _cnt = min(STAGE, _j1 - _c);                                  \
            __syncthreads();                                                  \
            for (int _i = tid; _i < _cnt; _i += TM) {                         \
                stA[_i] = refA[_c + _i];                                      \
                stB[_i] = refB[_c + _i];                                      \
            }                                                                 \
            __syncthreads();                                                  \
            const unsigned long long* _pA = (const unsigned long long*)stA;   \
            const unsigned long long* _pB = (const unsigned long long*)stB;   \
            _Pragma("unroll 4")                                               \
            for (int _j = 0; _j < _cnt; ++_j) {                               \
                unsigned long long _d =                                       \
                    fma2(qx2, _pA[2 * _j],                                    \
                         fma2(qy2, _pA[2 * _j + 1],                           \
                              fma2(qz2, _pB[2 * _j], _pB[2 * _j + 1])));      \
                float _d0, _d1;                                               \
                unpack2(_d, _d0, _d1);                                        \
                m0 = fminf(m0, _d0);                                          \
                m1 = fminf(m1, _d1);                                          \
            }                                                                 \
        }                                                                     \
    } while (0)

    int hm = bin_of(0.5f * (qlo + qhi));
    PROCESS_BIN(hm);

    int l = hm - 1, r = hm + 1;
    bool goL = (l >= 0), goR = (r < BINS);
    while (goL || goR) {
        // block-wide current max NN radius^2
        float r2 = fmaxf(fmaxf(m0 + qn0, m1 + qn1), 0.0f);
#pragma unroll
        for (int o = 16; o; o >>= 1) r2 = fmaxf(r2, __shfl_xor_sync(0xffffffffu, r2, o));
        if (lane == 0) sred[wid] = r2;
        __syncthreads();
        float rmax2 = fmaxf(fmaxf(sred[0], sred[1]), fmaxf(sred[2], sred[3]));
        __syncthreads();

        if (goL) {
            float dx = qlo - (XLO + (float)(l + 1) * XW);  // gap to bin l upper edge
            if (dx > 0.0f && dx * dx > rmax2) goL = false;
            else { PROCESS_BIN(l); --l; goL = (l >= 0); }
        }
        if (goR) {
            float dx = (XLO + (float)r * XW) - qhi;        // gap to bin r lower edge
            if (dx > 0.0f && dx * dx > rmax2) goR = false;
            else { PROCESS_BIN(r); ++r; goR = (r < BINS); }
        }
    }

    // finalize: sqrt(min d^2), block sum
    float s = sqrtf(fmaxf(m0 + qn0, 0.0f)) + sqrtf(fmaxf(m1 + qn1, 0.0f));
#pragma unroll
    for (int o = 16; o; o >>= 1) s += __shfl_xor_sync(0xffffffffu, s, o);
    __syncthreads();
    if (lane == 0) sred[wid] = s;
    __syncthreads();

    // Publish partial; last block to finish does the (deterministic) final sum.
    if (tid == 0) {
        g_part[bid] = sred[0] + sred[1] + sred[2] + sred[3];
        __threadfence();
        int old = atomicAdd(&g_ctr, 1);
        s_last = (old == NBLK - 1);
    }
    __syncthreads();
    if (s_last) {
        // 16 threads, one per (dir,batch); fixed-order serial sum per thread.
        __shared__ float bsum[16];
        if (tid < 16) {
            float acc = 0.0f;
#pragma unroll
            for (int i = 0; i < PT; ++i) acc += g_part[tid * PT + i];
            bsum[tid] = acc;
        }
        __syncthreads();
        if (tid == 0) {
            float comp = 0.0f, acc = 0.0f;
#pragma unroll
            for (int b = 0; b < NB; ++b) { comp += bsum[b]; acc += bsum[8 + b]; }
            comp *= (1.0f / (float)(NB * NP));
            acc  *= (1.0f / (float)(NB * NP));
            out[0] = acc;
            out[1] = comp;
            out[2] = 0.5f * (acc + comp);
        }
    }
#undef PROCESS_BIN
}

extern "C" void kernel_launch(void* const* d_in, const int* in_sizes, int n_in,
                              void* d_out, int out_size) {
    const float* tar = (const float*)d_in[0];
    const float* src = (const float*)d_in[1];
    float* out = (float*)d_out;

    cd_bucket<<<16, TB>>>(tar, src);
    cd_main<<<NBLK, TM>>>(out);
}